// round 14
// baseline (speedup 1.0000x reference)
#include <cuda_runtime.h>
#include <cstdint>

#define B_    2
#define QLEN  2048
#define HID   2048
#define NH    16
#define NKV   4
#define HD    128
#define BK    16

// Scratch (device globals are the sanctioned scratch mechanism)
__device__ float g_q [(size_t)B_ * NH * QLEN * HD];   // (b,h,q,d) 32MB, pre-RoPE
__device__ float g_ao[(size_t)B_ * QLEN * NH * HD];   // (b,q,h,d) 32MB

// tf32 round-to-nearest (unbiased; applied once at SMEM/fragment build time)
__device__ __forceinline__ float tf32r(float x) {
    unsigned u; asm("cvt.rna.tf32.f32 %0, %1;" : "=r"(u) : "f"(x));
    return __uint_as_float(u);
}
__device__ __forceinline__ unsigned tf32u(float x) {
    unsigned u; asm("cvt.rna.tf32.f32 %0, %1;" : "=r"(u) : "f"(x));
    return u;
}
__device__ __forceinline__ float4 tf32r4(float4 v) {
    return make_float4(tf32r(v.x), tf32r(v.y), tf32r(v.z), tf32r(v.w));
}

__device__ __forceinline__ void mma_tf32(float* c, const unsigned* a, const unsigned* b) {
    asm("mma.sync.aligned.m16n8k8.row.col.f32.tf32.tf32.f32 "
        "{%0,%1,%2,%3}, {%4,%5,%6,%7}, {%8,%9}, {%0,%1,%2,%3};"
        : "+f"(c[0]), "+f"(c[1]), "+f"(c[2]), "+f"(c[3])
        : "r"(a[0]), "r"(a[1]), "r"(a[2]), "r"(a[3]), "r"(b[0]), "r"(b[1]));
}

// ---------------------------------------------------------------------------
// 128x128 tf32 tensor-core GEMM, staging rebuilt for conflict-free STS and
// sector-exact LDG (R10's A/B stores had 2-way bank conflicts; B loader used
// 16 scalar LDGs). A staged m-major [128][20] (frag bank = 20*gid+tg, a 32-bank
// bijection; STS.128 bank quads tile 0..31). B staged [16][132] row-per-lane
// (frag bank = 4*tg+gid bijection; STS.128 quads 4*bk).
// 8 warps 2x4, warp tile 64x32 (R8/R9-established optimum), BK=16,
// double-buffered, one syncthreads per k-step.
// QMODE=1: scatter into g_q as (b,h,q,d) + bias. QMODE=0: row-major C.
// ---------------------------------------------------------------------------
#define ASTR 20
#define BSTR 132

template <int QMODE>
__global__ void __launch_bounds__(256, 2)
tgemm128(const float* __restrict__ A, const float* __restrict__ Bm,
         const float* __restrict__ bias, float* __restrict__ C,
         int M, int N, int K)
{
    __shared__ float As[2][128][ASTR];  // [m][k], tf32-rounded
    __shared__ float Bs[2][BK][BSTR];   // [k][n], tf32-rounded

    int tid = threadIdx.x;
    int w = tid >> 5, l = tid & 31;
    int wr = w >> 2, wc = w & 3;          // warp grid 2x4
    int gid = l >> 2, tg = l & 3;
    int bx = blockIdx.x, by = blockIdx.y;

    float c[4][4][4];
#pragma unroll
    for (int i = 0; i < 4; i++)
#pragma unroll
        for (int j = 0; j < 4; j++)
#pragma unroll
            for (int r = 0; r < 4; r++) c[i][j][r] = 0.f;

    // A loader: row-per-lane (clean STS banks; LDG 16B-sector cost is absorbed by idle L2)
    int ar = tid & 127, aq = (tid >> 7) * 8;
    // B loader: k-row-per-lane, 32B-aligned LDG sectors
    int bkr = tid & 15, bnq = (tid >> 4) * 8;
    const float* Ap = A + (size_t)(by * 128 + ar) * K + aq;
    const float* Bp = Bm + bx * 128 + bnq;

    float4 av0 = *(const float4*)(Ap);
    float4 av1 = *(const float4*)(Ap + 4);
    float4 bv0 = *(const float4*)(Bp + (size_t)bkr * N);
    float4 bv1 = *(const float4*)(Bp + (size_t)bkr * N + 4);

    // prologue store, buffer 0
    {
        *(float4*)&As[0][ar][aq]     = tf32r4(av0);
        *(float4*)&As[0][ar][aq + 4] = tf32r4(av1);
        *(float4*)&Bs[0][bkr][bnq]     = tf32r4(bv0);
        *(float4*)&Bs[0][bkr][bnq + 4] = tf32r4(bv1);
    }
    __syncthreads();

    int p = 0;
    for (int kt = 0; kt < K; kt += BK) {
        bool more = (kt + BK) < K;
        if (more) {
            av0 = *(const float4*)(Ap + kt + BK);
            av1 = *(const float4*)(Ap + kt + BK + 4);
            bv0 = *(const float4*)(Bp + (size_t)(kt + BK + bkr) * N);
            bv1 = *(const float4*)(Bp + (size_t)(kt + BK + bkr) * N + 4);
        }
#pragma unroll
        for (int ka = 0; ka < 2; ka++) {
            int kb = ka * 8;
            unsigned bf[4][2];
#pragma unroll
            for (int nj = 0; nj < 4; nj++) {
                int nb = wc * 32 + nj * 8 + gid;
                bf[nj][0] = __float_as_uint(Bs[p][kb + tg    ][nb]);
                bf[nj][1] = __float_as_uint(Bs[p][kb + tg + 4][nb]);
            }
#pragma unroll
            for (int mi = 0; mi < 4; mi++) {
                int mb = wr * 64 + mi * 16;
                unsigned af[4];
                af[0] = __float_as_uint(As[p][mb + gid    ][kb + tg]);
                af[1] = __float_as_uint(As[p][mb + gid + 8][kb + tg]);
                af[2] = __float_as_uint(As[p][mb + gid    ][kb + tg + 4]);
                af[3] = __float_as_uint(As[p][mb + gid + 8][kb + tg + 4]);
#pragma unroll
                for (int nj = 0; nj < 4; nj++)
                    mma_tf32(c[mi][nj], af, bf[nj]);
            }
        }
        if (more) {
            int q = p ^ 1;
            *(float4*)&As[q][ar][aq]     = tf32r4(av0);
            *(float4*)&As[q][ar][aq + 4] = tf32r4(av1);
            *(float4*)&Bs[q][bkr][bnq]     = tf32r4(bv0);
            *(float4*)&Bs[q][bkr][bnq + 4] = tf32r4(bv1);
            __syncthreads();
            p = q;
        }
    }

    // epilogue
#pragma unroll
    for (int mi = 0; mi < 4; mi++) {
#pragma unroll
        for (int nj = 0; nj < 4; nj++) {
            int row0 = by * 128 + wr * 64 + mi * 16 + gid;
            int col0 = bx * 128 + wc * 32 + nj * 8 + tg * 2;
            float b0 = bias ? bias[col0] : 0.f;
            float b1 = bias ? bias[col0 + 1] : 0.f;
            float2 v0 = make_float2(c[mi][nj][0] + b0, c[mi][nj][1] + b1);
            float2 v1 = make_float2(c[mi][nj][2] + b0, c[mi][nj][3] + b1);
            if (QMODE) {
                int b  = row0 >> 11, q = row0 & (QLEN - 1);
                int h  = col0 >> 7,  d = col0 & (HD - 1);
                *(float2*)&g_q[(((size_t)(b * NH + h)) * QLEN + q) * HD + d] = v0;
                int rb = (row0 + 8) >> 11, rq = (row0 + 8) & (QLEN - 1);
                *(float2*)&g_q[(((size_t)(rb * NH + h)) * QLEN + rq) * HD + d] = v1;
            } else {
                *(float2*)&C[(size_t)row0 * N + col0]       = v0;
                *(float2*)&C[(size_t)(row0 + 8) * N + col0] = v1;
            }
        }
    }
}

// ---------------------------------------------------------------------------
// Tensor-core glide attention with fused RoPE (unchanged from R10 — passing).
// ---------------------------------------------------------------------------
#define ATT2_SMEM_BYTES ((64*132 + 64*136 + 64*68) * 4)

__global__ void __launch_bounds__(128, 2)
attn_tc(const float* __restrict__ Kc, const float* __restrict__ Vc,
        const float* __restrict__ cosp, const float* __restrict__ sinp)
{
    extern __shared__ float sm[];
    float* Ks = sm;                 // [64][132]
    float* Vs = Ks + 64 * 132;      // [64][136]
    float* Ps = Vs + 64 * 136;      // [64][68]
    float* Qs = sm;                 // staging, aliases Ks

    const float SCALE = 0.08838834764831843f;

    int tid = threadIdx.x;
    int w = tid >> 5, l = tid & 31;
    int gid = l >> 2, tg = l & 3;
    int qi = (gridDim.x - 1) - blockIdx.x;
    int h = blockIdx.y, b = blockIdx.z;
    int q0 = qi * 64;
    int kvh = h >> 2;
    int qrow = w * 16;

    {
        const float* qg = &g_q[(((size_t)(b * NH + h)) * QLEN + q0) * HD];
        for (int i = tid; i < 64 * 16; i += 128) {
            int r = i >> 4, p4 = (i & 15) << 2;
            size_t cb = ((size_t)b * QLEN + q0 + r) * HD;
            float4 x1 = *(const float4*)&qg[r * HD + p4];
            float4 x2 = *(const float4*)&qg[r * HD + p4 + 64];
            float4 c1 = *(const float4*)&cosp[cb + p4];
            float4 s1 = *(const float4*)&sinp[cb + p4];
            float4 c2 = *(const float4*)&cosp[cb + p4 + 64];
            float4 s2 = *(const float4*)&sinp[cb + p4 + 64];
            *(float4*)&Qs[r * 132 + p4] = make_float4(
                x1.x * c1.x - x2.x * s1.x, x1.y * c1.y - x2.y * s1.y,
                x1.z * c1.z - x2.z * s1.z, x1.w * c1.w - x2.w * s1.w);
            *(float4*)&Qs[r * 132 + p4 + 64] = make_float4(
                x2.x * c2.x + x1.x * s2.x, x2.y * c2.y + x1.y * s2.y,
                x2.z * c2.z + x1.z * s2.z, x2.w * c2.w + x1.w * s2.w);
        }
    }
    __syncthreads();
    unsigned qa[16][4];
#pragma unroll
    for (int ks = 0; ks < 16; ks++) {
        int col = ks * 8 + tg;
        qa[ks][0] = tf32u(Qs[(qrow + gid    ) * 132 + col]);
        qa[ks][1] = tf32u(Qs[(qrow + gid + 8) * 132 + col]);
        qa[ks][2] = tf32u(Qs[(qrow + gid    ) * 132 + col + 4]);
        qa[ks][3] = tf32u(Qs[(qrow + gid + 8) * 132 + col + 4]);
    }

    float oc[16][4];
#pragma unroll
    for (int j = 0; j < 16; j++)
#pragma unroll
        for (int r = 0; r < 4; r++) oc[j][r] = 0.f;
    float m_run[2] = {-1e30f, -1e30f};
    float l_run[2] = {0.f, 0.f};

    int ntiles = qi + 1;

    for (int t = 0; t < ntiles; t++) {
        int k0 = t * 64;
        bool masked = (t == ntiles - 1);
        __syncthreads();

        for (int i = tid; i < 64 * 32; i += 128) {
            int r = i >> 5, c4 = (i & 31) << 2;
            size_t src = (((size_t)(b * QLEN) + k0 + r) * NKV + kvh) * HD + c4;
            *(float4*)&Ks[r * 132 + c4] = tf32r4(*(const float4*)&Kc[src]);
            *(float4*)&Vs[r * 136 + c4] = tf32r4(*(const float4*)&Vc[src]);
        }
        __syncthreads();

        float sc[8][4];
#pragma unroll
        for (int j = 0; j < 8; j++)
#pragma unroll
            for (int r = 0; r < 4; r++) sc[j][r] = 0.f;
#pragma unroll
        for (int ks = 0; ks < 16; ks++) {
            int d0 = ks * 8 + tg;
#pragma unroll
            for (int j = 0; j < 8; j++) {
                unsigned bf[2];
                bf[0] = __float_as_uint(Ks[(j * 8 + gid) * 132 + d0]);
                bf[1] = __float_as_uint(Ks[(j * 8 + gid) * 132 + d0 + 4]);
                mma_tf32(sc[j], qa[ks], bf);
            }
        }

        float alpha_h[2];
#pragma unroll
        for (int hf = 0; hf < 2; hf++) {
            int rowq = q0 + qrow + gid + hf * 8;
            int kend = masked ? ((rowq < 4) ? 4 : (rowq & ~3)) : (1 << 30);
            float mx = -1e30f;
#pragma unroll
            for (int j = 0; j < 8; j++) {
#pragma unroll
                for (int cc = 0; cc < 2; cc++) {
                    float v = sc[j][hf * 2 + cc] * SCALE;
                    int col = k0 + j * 8 + tg * 2 + cc;
                    if (col >= kend) v = -1e30f;
                    sc[j][hf * 2 + cc] = v;
                    mx = fmaxf(mx, v);
                }
            }
            mx = fmaxf(mx, __shfl_xor_sync(0xffffffffu, mx, 1));
            mx = fmaxf(mx, __shfl_xor_sync(0xffffffffu, mx, 2));
            float mn = fmaxf(m_run[hf], mx);
            float al = __expf(m_run[hf] - mn);
            m_run[hf] = mn;
            float sum = 0.f;
#pragma unroll
            for (int j = 0; j < 8; j++) {
                float p0 = tf32r(__expf(sc[j][hf * 2]     - mn));
                float p1 = tf32r(__expf(sc[j][hf * 2 + 1] - mn));
                sum += p0 + p1;
                *(float2*)&Ps[(qrow + gid + hf * 8) * 68 + j * 8 + tg * 2] =
                    make_float2(p0, p1);
            }
            sum += __shfl_xor_sync(0xffffffffu, sum, 1);
            sum += __shfl_xor_sync(0xffffffffu, sum, 2);
            l_run[hf] = l_run[hf] * al + sum;
            alpha_h[hf] = al;
        }
        __syncwarp();

#pragma unroll
        for (int j = 0; j < 16; j++) {
            oc[j][0] *= alpha_h[0]; oc[j][1] *= alpha_h[0];
            oc[j][2] *= alpha_h[1]; oc[j][3] *= alpha_h[1];
        }

#pragma unroll
        for (int kbi = 0; kbi < 8; kbi++) {
            int kb = kbi * 8;
            unsigned af[4];
            af[0] = __float_as_uint(Ps[(qrow + gid    ) * 68 + kb + tg]);
            af[1] = __float_as_uint(Ps[(qrow + gid + 8) * 68 + kb + tg]);
            af[2] = __float_as_uint(Ps[(qrow + gid    ) * 68 + kb + tg + 4]);
            af[3] = __float_as_uint(Ps[(qrow + gid + 8) * 68 + kb + tg + 4]);
#pragma unroll
            for (int j = 0; j < 16; j++) {
                unsigned bf[2];
                bf[0] = __float_as_uint(Vs[(kb + tg    ) * 136 + j * 8 + gid]);
                bf[1] = __float_as_uint(Vs[(kb + tg + 4) * 136 + j * 8 + gid]);
                mma_tf32(oc[j], af, bf);
            }
        }
    }

    float inv0 = 1.0f / l_run[0];
    float inv1 = 1.0f / l_run[1];
    int row0 = q0 + qrow + gid;
#pragma unroll
    for (int j = 0; j < 16; j++) {
        int d = j * 8 + tg * 2;
        *(float2*)&g_ao[(((size_t)b * QLEN + row0) * NH + h) * HD + d] =
            make_float2(oc[j][0] * inv0, oc[j][1] * inv0);
        *(float2*)&g_ao[(((size_t)b * QLEN + row0 + 8) * NH + h) * HD + d] =
            make_float2(oc[j][2] * inv1, oc[j][3] * inv1);
    }
}

// ---------------------------------------------------------------------------
extern "C" void kernel_launch(void* const* d_in, const int* in_sizes, int n_in,
                              void* d_out, int out_size)
{
    const float* X    = (const float*)d_in[0];
    const float* Kc   = (const float*)d_in[1];
    const float* Vc   = (const float*)d_in[2];
    const float* cosp = (const float*)d_in[3];
    const float* sinp = (const float*)d_in[4];
    const float* Wq   = (const float*)d_in[5];
    const float* bq   = (const float*)d_in[6];
    const float* Wo   = (const float*)d_in[7];
    float* out = (float*)d_out;

    void* gaop;
    cudaGetSymbolAddress(&gaop, g_ao);

    // 1) Q projection (tf32 tensor cores) + bias, scattered to (b,h,q,d)
    tgemm128<1><<<dim3(HID / 128, (B_ * QLEN) / 128), 256>>>(
        X, Wq, bq, nullptr, B_ * QLEN, NH * HD, HID);

    // 2) glide attention (tensor cores, tf32-RN operands, fused RoPE)
    cudaFuncSetAttribute(attn_tc, cudaFuncAttributeMaxDynamicSharedMemorySize,
                         ATT2_SMEM_BYTES);
    attn_tc<<<dim3(QLEN / 64, NH, B_), 128, ATT2_SMEM_BYTES>>>(Kc, Vc, cosp, sinp);

    // 3) output projection (tf32 tensor cores)
    tgemm128<0><<<dim3(HID / 128, (B_ * QLEN) / 128), 256>>>(
        (const float*)gaop, Wo, nullptr, out, B_ * QLEN, HID, NH * HD);
}

// round 16
// speedup vs baseline: 1.3918x; 1.3918x over previous
#include <cuda_runtime.h>
#include <cstdint>

#define B_    2
#define QLEN  2048
#define HID   2048
#define NH    16
#define NKV   4
#define HD    128
#define BK    16

// Scratch (device globals are the sanctioned scratch mechanism)
__device__ float g_q [(size_t)B_ * NH * QLEN * HD];   // (b,h,q,d) 32MB, pre-RoPE
__device__ float g_ao[(size_t)B_ * QLEN * NH * HD];   // (b,q,h,d) 32MB

// tf32 round-to-nearest (unbiased; applied once at SMEM/fragment build time)
__device__ __forceinline__ float tf32r(float x) {
    unsigned u; asm("cvt.rna.tf32.f32 %0, %1;" : "=r"(u) : "f"(x));
    return __uint_as_float(u);
}
__device__ __forceinline__ unsigned tf32u(float x) {
    unsigned u; asm("cvt.rna.tf32.f32 %0, %1;" : "=r"(u) : "f"(x));
    return u;
}
__device__ __forceinline__ float4 tf32r4(float4 v) {
    return make_float4(tf32r(v.x), tf32r(v.y), tf32r(v.z), tf32r(v.w));
}

__device__ __forceinline__ void mma_tf32(float* c, const unsigned* a, const unsigned* b) {
    asm("mma.sync.aligned.m16n8k8.row.col.f32.tf32.tf32.f32 "
        "{%0,%1,%2,%3}, {%4,%5,%6,%7}, {%8,%9}, {%0,%1,%2,%3};"
        : "+f"(c[0]), "+f"(c[1]), "+f"(c[2]), "+f"(c[3])
        : "r"(a[0]), "r"(a[1]), "r"(a[2]), "r"(a[3]), "r"(b[0]), "r"(b[1]));
}

// ---------------------------------------------------------------------------
// 128x128 tf32 tensor-core GEMM — EXACT R10 configuration (366us measured 3x;
// R11's "improved" staging regressed to 574us via scattered row-per-lane LDG).
// 8 warps 2x4, warp tile 64x32, BK=16, stride-136 double-buffered SMEM.
// QMODE=1: scatter into g_q as (b,h,q,d) + bias. QMODE=0: row-major C.
// ---------------------------------------------------------------------------
#define GSTR 136

template <int QMODE>
__global__ void __launch_bounds__(256, 2)
tgemm128(const float* __restrict__ A, const float* __restrict__ Bm,
         const float* __restrict__ bias, float* __restrict__ C,
         int M, int N, int K)
{
    __shared__ float As[2][BK][GSTR];   // [k][m], tf32-rounded
    __shared__ float Bs[2][BK][GSTR];   // [k][n], tf32-rounded

    int tid = threadIdx.x;
    int w = tid >> 5, l = tid & 31;
    int wr = w >> 2, wc = w & 3;          // warp grid 2x4
    int gid = l >> 2, tg = l & 3;
    int bx = blockIdx.x, by = blockIdx.y;

    float c[4][4][4];
#pragma unroll
    for (int i = 0; i < 4; i++)
#pragma unroll
        for (int j = 0; j < 4; j++)
#pragma unroll
            for (int r = 0; r < 4; r++) c[i][j][r] = 0.f;

    int am = tid >> 1, ak = (tid & 1) * 8;   // A loader: 128 rows x 16 k
    int bk = tid >> 4, bn = (tid & 15) * 8;  // B loader: 16 k x 128 n
    const float* Ap = A + (size_t)(by * 128 + am) * K + ak;
    const float* Bp = Bm + (size_t)bk * N + bx * 128 + bn;

    float4 av0 = *(const float4*)(Ap);
    float4 av1 = *(const float4*)(Ap + 4);
    float4 bv0 = *(const float4*)(Bp);
    float4 bv1 = *(const float4*)(Bp + 4);

    // prologue store, buffer 0
    {
        As[0][ak+0][am] = tf32r(av0.x); As[0][ak+1][am] = tf32r(av0.y);
        As[0][ak+2][am] = tf32r(av0.z); As[0][ak+3][am] = tf32r(av0.w);
        As[0][ak+4][am] = tf32r(av1.x); As[0][ak+5][am] = tf32r(av1.y);
        As[0][ak+6][am] = tf32r(av1.z); As[0][ak+7][am] = tf32r(av1.w);
        *(float4*)&Bs[0][bk][bn]     = tf32r4(bv0);
        *(float4*)&Bs[0][bk][bn + 4] = tf32r4(bv1);
    }
    __syncthreads();

    int p = 0;
    for (int kt = 0; kt < K; kt += BK) {
        bool more = (kt + BK) < K;
        if (more) {
            av0 = *(const float4*)(Ap + kt + BK);
            av1 = *(const float4*)(Ap + kt + BK + 4);
            bv0 = *(const float4*)(Bp + (size_t)(kt + BK) * N);
            bv1 = *(const float4*)(Bp + (size_t)(kt + BK) * N + 4);
        }
#pragma unroll
        for (int ka = 0; ka < 2; ka++) {
            int kb = ka * 8;
            unsigned bf[4][2];
#pragma unroll
            for (int nj = 0; nj < 4; nj++) {
                int nb = wc * 32 + nj * 8 + gid;
                bf[nj][0] = __float_as_uint(Bs[p][kb + tg    ][nb]);
                bf[nj][1] = __float_as_uint(Bs[p][kb + tg + 4][nb]);
            }
#pragma unroll
            for (int mi = 0; mi < 4; mi++) {
                int mb = wr * 64 + mi * 16;
                unsigned af[4];
                af[0] = __float_as_uint(As[p][kb + tg    ][mb + gid]);
                af[1] = __float_as_uint(As[p][kb + tg    ][mb + gid + 8]);
                af[2] = __float_as_uint(As[p][kb + tg + 4][mb + gid]);
                af[3] = __float_as_uint(As[p][kb + tg + 4][mb + gid + 8]);
#pragma unroll
                for (int nj = 0; nj < 4; nj++)
                    mma_tf32(c[mi][nj], af, bf[nj]);
            }
        }
        if (more) {
            int q = p ^ 1;
            As[q][ak+0][am] = tf32r(av0.x); As[q][ak+1][am] = tf32r(av0.y);
            As[q][ak+2][am] = tf32r(av0.z); As[q][ak+3][am] = tf32r(av0.w);
            As[q][ak+4][am] = tf32r(av1.x); As[q][ak+5][am] = tf32r(av1.y);
            As[q][ak+6][am] = tf32r(av1.z); As[q][ak+7][am] = tf32r(av1.w);
            *(float4*)&Bs[q][bk][bn]     = tf32r4(bv0);
            *(float4*)&Bs[q][bk][bn + 4] = tf32r4(bv1);
            __syncthreads();
            p = q;
        }
    }

    // epilogue
#pragma unroll
    for (int mi = 0; mi < 4; mi++) {
#pragma unroll
        for (int nj = 0; nj < 4; nj++) {
            int row0 = by * 128 + wr * 64 + mi * 16 + gid;
            int col0 = bx * 128 + wc * 32 + nj * 8 + tg * 2;
            float b0 = bias ? bias[col0] : 0.f;
            float b1 = bias ? bias[col0 + 1] : 0.f;
            float2 v0 = make_float2(c[mi][nj][0] + b0, c[mi][nj][1] + b1);
            float2 v1 = make_float2(c[mi][nj][2] + b0, c[mi][nj][3] + b1);
            if (QMODE) {
                int b  = row0 >> 11, q = row0 & (QLEN - 1);
                int h  = col0 >> 7,  d = col0 & (HD - 1);
                *(float2*)&g_q[(((size_t)(b * NH + h)) * QLEN + q) * HD + d] = v0;
                int rb = (row0 + 8) >> 11, rq = (row0 + 8) & (QLEN - 1);
                *(float2*)&g_q[(((size_t)(rb * NH + h)) * QLEN + rq) * HD + d] = v1;
            } else {
                *(float2*)&C[(size_t)row0 * N + col0]       = v0;
                *(float2*)&C[(size_t)(row0 + 8) * N + col0] = v1;
            }
        }
    }
}

// ---------------------------------------------------------------------------
// Tensor-core glide attention, 128-QUERY tile (256 thr, 8 warps x 16 rows).
// K/V tiles stay 64 keys, so each staged K/V tile now feeds 2x the MMA work:
// load instrs, tf32 cvts, and barriers per unit compute all halve vs R10.
// Warp-local softmax, fragment layouts, masking, and K-tile order unchanged
// -> bit-identical numerics. masked iff t >= 2*qi (tiles below q0 are fully
// live since kend(row) >= q0). Fused RoPE at Q staging. LPT: heavy CTAs first.
// ---------------------------------------------------------------------------
#define ATT3_SMEM_BYTES ((64*132 + 64*136 + 128*68) * 4)   // K,V,P = 101KB

__global__ void __launch_bounds__(256, 1)
attn_tc(const float* __restrict__ Kc, const float* __restrict__ Vc,
        const float* __restrict__ cosp, const float* __restrict__ sinp)
{
    extern __shared__ float sm[];
    float* Ks = sm;                 // [64][132]  keys, tf32-RN
    float* Vs = Ks + 64 * 132;      // [64][136]  values, tf32-RN
    float* Ps = Vs + 64 * 136;      // [128][68]  probs, tf32-RN
    float* Qs = sm;                 // Q staging [128][132], aliases Ks+Vs (67.6KB<=68.6KB)

    const float SCALE = 0.08838834764831843f;  // 128^-0.5

    int tid = threadIdx.x;
    int w = tid >> 5, l = tid & 31;
    int gid = l >> 2, tg = l & 3;
    int qi = (gridDim.x - 1) - blockIdx.x;   // heavy tiles first
    int h = blockIdx.y, b = blockIdx.z;
    int q0 = qi * 128;
    int kvh = h >> 2;
    int qrow = w * 16;                        // warp's q base within tile

    // stage Q with fused RoPE into Qs[128][132]
    {
        const float* qg = &g_q[(((size_t)(b * NH + h)) * QLEN + q0) * HD];
        for (int i = tid; i < 128 * 16; i += 256) {
            int r = i >> 4, p4 = (i & 15) << 2;        // row, pair-col (d<64)
            size_t cb = ((size_t)b * QLEN + q0 + r) * HD;
            float4 x1 = *(const float4*)&qg[r * HD + p4];
            float4 x2 = *(const float4*)&qg[r * HD + p4 + 64];
            float4 c1 = *(const float4*)&cosp[cb + p4];
            float4 s1 = *(const float4*)&sinp[cb + p4];
            float4 c2 = *(const float4*)&cosp[cb + p4 + 64];
            float4 s2 = *(const float4*)&sinp[cb + p4 + 64];
            *(float4*)&Qs[r * 132 + p4] = make_float4(
                x1.x * c1.x - x2.x * s1.x, x1.y * c1.y - x2.y * s1.y,
                x1.z * c1.z - x2.z * s1.z, x1.w * c1.w - x2.w * s1.w);
            *(float4*)&Qs[r * 132 + p4 + 64] = make_float4(
                x2.x * c2.x + x1.x * s2.x, x2.y * c2.y + x1.y * s2.y,
                x2.z * c2.z + x1.z * s2.z, x2.w * c2.w + x1.w * s2.w);
        }
    }
    __syncthreads();
    unsigned qa[16][4];
#pragma unroll
    for (int ks = 0; ks < 16; ks++) {
        int col = ks * 8 + tg;
        qa[ks][0] = tf32u(Qs[(qrow + gid    ) * 132 + col]);
        qa[ks][1] = tf32u(Qs[(qrow + gid + 8) * 132 + col]);
        qa[ks][2] = tf32u(Qs[(qrow + gid    ) * 132 + col + 4]);
        qa[ks][3] = tf32u(Qs[(qrow + gid + 8) * 132 + col + 4]);
    }

    float oc[16][4];
#pragma unroll
    for (int j = 0; j < 16; j++)
#pragma unroll
        for (int r = 0; r < 4; r++) oc[j][r] = 0.f;
    float m_run[2] = {-1e30f, -1e30f};
    float l_run[2] = {0.f, 0.f};

    int ntiles = 2 * qi + 2;

    for (int t = 0; t < ntiles; t++) {
        int k0 = t * 64;
        bool masked = (t >= 2 * qi);
        __syncthreads();   // previous tile's Ks/Vs readers done (also covers Qs)

        // load K,V tiles, tf32-RN at store (row = key, d contiguous)
        for (int i = tid; i < 64 * 32; i += 256) {
            int r = i >> 5, c4 = (i & 31) << 2;
            size_t src = (((size_t)(b * QLEN) + k0 + r) * NKV + kvh) * HD + c4;
            *(float4*)&Ks[r * 132 + c4] = tf32r4(*(const float4*)&Kc[src]);
            *(float4*)&Vs[r * 136 + c4] = tf32r4(*(const float4*)&Vc[src]);
        }
        __syncthreads();

        // ---- S = Q K^T : 16 k-steps(d) x 8 n-atoms(keys) ----
        float sc[8][4];
#pragma unroll
        for (int j = 0; j < 8; j++)
#pragma unroll
            for (int r = 0; r < 4; r++) sc[j][r] = 0.f;
#pragma unroll
        for (int ks = 0; ks < 16; ks++) {
            int d0 = ks * 8 + tg;
#pragma unroll
            for (int j = 0; j < 8; j++) {
                unsigned bf[2];
                bf[0] = __float_as_uint(Ks[(j * 8 + gid) * 132 + d0]);
                bf[1] = __float_as_uint(Ks[(j * 8 + gid) * 132 + d0 + 4]);
                mma_tf32(sc[j], qa[ks], bf);
            }
        }

        // ---- warp-local online softmax (rows gid, gid+8) ----
        float alpha_h[2];
#pragma unroll
        for (int hf = 0; hf < 2; hf++) {
            int rowq = q0 + qrow + gid + hf * 8;
            int kend = masked ? ((rowq < 4) ? 4 : (rowq & ~3)) : (1 << 30);
            float mx = -1e30f;
#pragma unroll
            for (int j = 0; j < 8; j++) {
#pragma unroll
                for (int cc = 0; cc < 2; cc++) {
                    float v = sc[j][hf * 2 + cc] * SCALE;
                    int col = k0 + j * 8 + tg * 2 + cc;
                    if (col >= kend) v = -1e30f;
                    sc[j][hf * 2 + cc] = v;
                    mx = fmaxf(mx, v);
                }
            }
            mx = fmaxf(mx, __shfl_xor_sync(0xffffffffu, mx, 1));
            mx = fmaxf(mx, __shfl_xor_sync(0xffffffffu, mx, 2));
            float mn = fmaxf(m_run[hf], mx);
            float al = __expf(m_run[hf] - mn);
            m_run[hf] = mn;
            float sum = 0.f;
#pragma unroll
            for (int j = 0; j < 8; j++) {
                // round P to tf32 BEFORE summing so l_run matches the PV numerator
                float p0 = tf32r(__expf(sc[j][hf * 2]     - mn));
                float p1 = tf32r(__expf(sc[j][hf * 2 + 1] - mn));
                sum += p0 + p1;
                *(float2*)&Ps[(qrow + gid + hf * 8) * 68 + j * 8 + tg * 2] =
                    make_float2(p0, p1);
            }
            sum += __shfl_xor_sync(0xffffffffu, sum, 1);
            sum += __shfl_xor_sync(0xffffffffu, sum, 2);
            l_run[hf] = l_run[hf] * al + sum;
            alpha_h[hf] = al;
        }
        __syncwarp();   // Ps rows are warp-exclusive; order STS -> LDS in-warp

        // rescale running O
#pragma unroll
        for (int j = 0; j < 16; j++) {
            oc[j][0] *= alpha_h[0]; oc[j][1] *= alpha_h[0];
            oc[j][2] *= alpha_h[1]; oc[j][3] *= alpha_h[1];
        }

        // ---- O += P V : 8 k-steps(keys) x 16 n-atoms(d) ----
#pragma unroll
        for (int kbi = 0; kbi < 8; kbi++) {
            int kb = kbi * 8;
            unsigned af[4];
            af[0] = __float_as_uint(Ps[(qrow + gid    ) * 68 + kb + tg]);
            af[1] = __float_as_uint(Ps[(qrow + gid + 8) * 68 + kb + tg]);
            af[2] = __float_as_uint(Ps[(qrow + gid    ) * 68 + kb + tg + 4]);
            af[3] = __float_as_uint(Ps[(qrow + gid + 8) * 68 + kb + tg + 4]);
#pragma unroll
            for (int j = 0; j < 16; j++) {
                unsigned bf[2];
                bf[0] = __float_as_uint(Vs[(kb + tg    ) * 136 + j * 8 + gid]);
                bf[1] = __float_as_uint(Vs[(kb + tg + 4) * 136 + j * 8 + gid]);
                mma_tf32(oc[j], af, bf);
            }
        }
    }

    // normalize + store to (b,q,h,d)
    float inv0 = 1.0f / l_run[0];
    float inv1 = 1.0f / l_run[1];
    int row0 = q0 + qrow + gid;
#pragma unroll
    for (int j = 0; j < 16; j++) {
        int d = j * 8 + tg * 2;
        *(float2*)&g_ao[(((size_t)b * QLEN + row0) * NH + h) * HD + d] =
            make_float2(oc[j][0] * inv0, oc[j][1] * inv0);
        *(float2*)&g_ao[(((size_t)b * QLEN + row0 + 8) * NH + h) * HD + d] =
            make_float2(oc[j][2] * inv1, oc[j][3] * inv1);
    }
}

// ---------------------------------------------------------------------------
extern "C" void kernel_launch(void* const* d_in, const int* in_sizes, int n_in,
                              void* d_out, int out_size)
{
    const float* X    = (const float*)d_in[0];
    const float* Kc   = (const float*)d_in[1];
    const float* Vc   = (const float*)d_in[2];
    const float* cosp = (const float*)d_in[3];
    const float* sinp = (const float*)d_in[4];
    const float* Wq   = (const float*)d_in[5];
    const float* bq   = (const float*)d_in[6];
    const float* Wo   = (const float*)d_in[7];
    float* out = (float*)d_out;

    void* gaop;
    cudaGetSymbolAddress(&gaop, g_ao);

    // 1) Q projection (tf32 tensor cores) + bias, scattered to (b,h,q,d)
    tgemm128<1><<<dim3(HID / 128, (B_ * QLEN) / 128), 256>>>(
        X, Wq, bq, nullptr, B_ * QLEN, NH * HD, HID);

    // 2) glide attention (tensor cores, tf32-RN operands, fused RoPE, 128-q tiles)
    cudaFuncSetAttribute(attn_tc, cudaFuncAttributeMaxDynamicSharedMemorySize,
                         ATT3_SMEM_BYTES);
    attn_tc<<<dim3(QLEN / 128, NH, B_), 256, ATT3_SMEM_BYTES>>>(Kc, Vc, cosp, sinp);

    // 3) output projection (tf32 tensor cores)
    tgemm128<0><<<dim3(HID / 128, (B_ * QLEN) / 128), 256>>>(
        (const float*)gaop, Wo, nullptr, out, B_ * QLEN, HID, NH * HD);
}